// round 7
// baseline (speedup 1.0000x reference)
#include <cuda_runtime.h>
#include <cuda_bf16.h>
#include <math.h>

// Problem constants (from reference): N=50000, E=800000, dims all 128.
#define MAXN 50000
#define MAXE 800000
#define D 128

// Scratch (no allocations allowed -> __device__ globals). 16B-aligned for float4.
__device__ __align__(16) float g_semn[MAXN * D];   // normalized semantic vectors
__device__ __align__(16) float g_agg[MAXN * D];    // softmax-weighted aggregate per dst
__device__ __align__(16) float g_Wt[D * D];        // W_src^T: Wt[k*128+j] = W[j*128+k]
__device__ float g_bcoef[MAXN];                    // sum(attn) per dst (~1 or 0)
__device__ int   g_deg[MAXN];
__device__ int   g_offs[MAXN + 1];
__device__ int   g_cursor[MAXN];
__device__ int   g_srcs[MAXE];                     // src node per edge, grouped by dst
__device__ int   g_is64;                           // edge_index dtype flag

// ---------------------------------------------------------------------------
// K-1: detect whether edge_index buffer is int64 or int32.
// int64 values < 50000 => every odd 32-bit word (high word) is 0.
// int32 => odd positions are random edge ids, essentially never all zero.
// ---------------------------------------------------------------------------
__global__ void detect_kernel(const int* __restrict__ p32, int e) {
    __shared__ int nz;
    int tid = threadIdx.x;
    if (tid == 0) nz = 0;
    __syncthreads();
    int idx = 2 * tid + 1;              // sample 128 odd words
    if (idx < 2 * e && p32[idx] != 0) atomicAdd(&nz, 1);
    __syncthreads();
    if (tid == 0) g_is64 = (nz == 0) ? 1 : 0;
}

__device__ __forceinline__ int edge_val(const void* ei, int e, int idx) {
    if (g_is64) return (int)((const long long*)ei)[idx];
    return ((const int*)ei)[idx];
}

// ---------------------------------------------------------------------------
// K0: zero histogram + transpose W
// ---------------------------------------------------------------------------
__global__ void prep_kernel(const float* __restrict__ W, int n) {
    int i = blockIdx.x * blockDim.x + threadIdx.x;
    if (i < n) g_deg[i] = 0;
    if (i < D * D) {
        int j = i >> 7;      // row of W
        int k = i & 127;     // col of W
        g_Wt[k * D + j] = W[i];
    }
}

// ---------------------------------------------------------------------------
// K1: normalized semantic vectors (warp per node, 4 floats/lane)
// ---------------------------------------------------------------------------
__global__ __launch_bounds__(256) void norm_kernel(const float* __restrict__ sem, int n) {
    int warp = (blockIdx.x * blockDim.x + threadIdx.x) >> 5;
    int lane = threadIdx.x & 31;
    if (warp >= n) return;
    float4 v = ((const float4*)sem)[(size_t)warp * 32 + lane];
    float ss = v.x * v.x + v.y * v.y + v.z * v.z + v.w * v.w;
    #pragma unroll
    for (int o = 16; o; o >>= 1) ss += __shfl_xor_sync(0xffffffffu, ss, o);
    float inv = 1.0f / fmaxf(sqrtf(ss), 1e-8f);
    ((float4*)g_semn)[(size_t)warp * 32 + lane] =
        make_float4(v.x * inv, v.y * inv, v.z * inv, v.w * inv);
}

// ---------------------------------------------------------------------------
// K2: degree histogram over dst (range-guarded: a bad index can never trap)
// ---------------------------------------------------------------------------
__global__ void hist_kernel(const void* __restrict__ ei, int e, int n) {
    int i = blockIdx.x * blockDim.x + threadIdx.x;
    if (i >= e) return;
    int d = edge_val(ei, e, e + i);
    if ((unsigned)d < (unsigned)n) atomicAdd(&g_deg[d], 1);
}

// ---------------------------------------------------------------------------
// K3: exclusive scan of degrees (single block, chunked Hillis-Steele)
// ---------------------------------------------------------------------------
__global__ void scan_kernel(int n) {
    __shared__ int sh[1024];
    __shared__ int carry_sh;
    int tid = threadIdx.x;
    int carry = 0;
    for (int base = 0; base < n; base += 1024) {
        int i = base + tid;
        int v = (i < n) ? g_deg[i] : 0;
        sh[tid] = v;
        __syncthreads();
        for (int off = 1; off < 1024; off <<= 1) {
            int t = (tid >= off) ? sh[tid - off] : 0;
            __syncthreads();
            sh[tid] += t;
            __syncthreads();
        }
        int incl = sh[tid];
        int excl = carry + incl - v;
        if (i < n) { g_offs[i] = excl; g_cursor[i] = excl; }
        if (tid == 1023) carry_sh = carry + incl;
        __syncthreads();
        carry = carry_sh;
        __syncthreads();
    }
    if (tid == 0) g_offs[n] = carry;
}

// ---------------------------------------------------------------------------
// K4: counting-sort scatter of src ids grouped by dst
// ---------------------------------------------------------------------------
__global__ void scatter_kernel(const void* __restrict__ ei, int e, int n) {
    int i = blockIdx.x * blockDim.x + threadIdx.x;
    if (i >= e) return;
    int s = edge_val(ei, e, i);
    int d = edge_val(ei, e, e + i);
    if ((unsigned)s >= (unsigned)n || (unsigned)d >= (unsigned)n) return;
    int pos = atomicAdd(&g_cursor[d], 1);
    g_srcs[pos] = s;
}

// ---------------------------------------------------------------------------
// K5: per-dst online-softmax aggregation (warp per dst node)
//     acc = sum_e exp(sim_e - max) * x[src_e];  s = sum_e exp(sim_e - max)
//     agg = acc / (s + 1e-16);  bcoef = s / (s + 1e-16)
// ---------------------------------------------------------------------------
__global__ __launch_bounds__(256) void agg_kernel(const float* __restrict__ x, int n) {
    int warp = (blockIdx.x * blockDim.x + threadIdx.x) >> 5;
    int lane = threadIdx.x & 31;
    if (warp >= n) return;
    int d = warp;
    int beg = g_offs[d];
    int end = g_offs[d + 1];

    const float4* semn4 = (const float4*)g_semn;
    const float4* x4    = (const float4*)x;

    float4 sd = semn4[(size_t)d * 32 + lane];

    float m = -INFINITY;
    float s = 0.0f;
    float4 acc = make_float4(0.f, 0.f, 0.f, 0.f);

    for (int i = beg; i < end; ++i) {
        int src = g_srcs[i];
        float4 sv = semn4[(size_t)src * 32 + lane];
        float p = sd.x * sv.x + sd.y * sv.y + sd.z * sv.z + sd.w * sv.w;
        #pragma unroll
        for (int o = 16; o; o >>= 1) p += __shfl_xor_sync(0xffffffffu, p, o);

        float4 xv = x4[(size_t)src * 32 + lane];

        if (p > m) {
            float r = __expf(m - p);   // 0 on first iteration (m = -inf)
            s *= r;
            acc.x *= r; acc.y *= r; acc.z *= r; acc.w *= r;
            m = p;
        }
        float w = __expf(p - m);
        s += w;
        acc.x += w * xv.x; acc.y += w * xv.y;
        acc.z += w * xv.z; acc.w += w * xv.w;
    }

    float inv = 1.0f / (s + 1e-16f);
    ((float4*)g_agg)[(size_t)d * 32 + lane] =
        make_float4(acc.x * inv, acc.y * inv, acc.z * inv, acc.w * inv);
    if (lane == 0) g_bcoef[d] = s * inv;
}

// ---------------------------------------------------------------------------
// K6: out[d] = agg[d] @ W^T + bcoef[d] * b
//     A-tile (64 rows, 32KB) in static shared; Wt streamed from global via
//     __ldg (64KB, L1-resident after first pass; 1 LDG.128 per 16 FFMA).
//     Warp: 8 rows in 2 groups of 4; lane owns columns lane*4..lane*4+3.
// ---------------------------------------------------------------------------
#define GR 64
__global__ __launch_bounds__(256) void gemm_kernel(const float* __restrict__ bias,
                                                   float* __restrict__ out, int n) {
    __shared__ float shA[GR * D];    // 32 KB
    __shared__ float shB[D];

    int tid = threadIdx.x;
    int rbase = blockIdx.x * GR;

    if (tid < D) shB[tid] = bias[tid];
    for (int i = tid; i < GR * 32; i += 256) {
        int r = rbase + (i >> 5);
        ((float4*)shA)[i] = (r < n) ? ((const float4*)g_agg)[(size_t)rbase * 32 + i]
                                    : make_float4(0.f, 0.f, 0.f, 0.f);
    }
    __syncthreads();

    int warp = tid >> 5, lane = tid & 31;
    const float4* Wt4 = (const float4*)g_Wt;   // row k -> 32 float4 (cols)

    #pragma unroll
    for (int g = 0; g < 2; ++g) {
        int rr0 = warp * 8 + g * 4;
        float acc[4][4];
        #pragma unroll
        for (int r = 0; r < 4; r++)
            #pragma unroll
            for (int c = 0; c < 4; c++) acc[r][c] = 0.f;

        #pragma unroll 4
        for (int k = 0; k < D; k += 4) {
            float4 w0 = __ldg(&Wt4[(k + 0) * 32 + lane]);
            float4 w1 = __ldg(&Wt4[(k + 1) * 32 + lane]);
            float4 w2 = __ldg(&Wt4[(k + 2) * 32 + lane]);
            float4 w3 = __ldg(&Wt4[(k + 3) * 32 + lane]);
            #pragma unroll
            for (int r = 0; r < 4; r++) {
                float4 a = *(const float4*)(shA + (rr0 + r) * D + k);  // broadcast
                acc[r][0] += a.x * w0.x + a.y * w1.x + a.z * w2.x + a.w * w3.x;
                acc[r][1] += a.x * w0.y + a.y * w1.y + a.z * w2.y + a.w * w3.y;
                acc[r][2] += a.x * w0.z + a.y * w1.z + a.z * w2.z + a.w * w3.z;
                acc[r][3] += a.x * w0.w + a.y * w1.w + a.z * w2.w + a.w * w3.w;
            }
        }

        #pragma unroll
        for (int r = 0; r < 4; r++) {
            int row = rbase + rr0 + r;
            if (row >= n) break;
            float bc = g_bcoef[row];
            float4 o;
            o.x = acc[r][0] + bc * shB[lane * 4 + 0];
            o.y = acc[r][1] + bc * shB[lane * 4 + 1];
            o.z = acc[r][2] + bc * shB[lane * 4 + 2];
            o.w = acc[r][3] + bc * shB[lane * 4 + 3];
            ((float4*)out)[(size_t)row * 32 + lane] = o;
        }
    }
}

// ---------------------------------------------------------------------------
// Launch.
// Inputs (metadata order): x[N,128] f32, edge_index[2,E] (int32 or int64),
//   semantic_vec[N,128] f32, W_src[128,128] f32, b_src[128] f32,
//   W_dst (unused), b_dst (unused).
// Output: out[N,128] f32.
// Key algebraic fact: out = (sum_e attn*x[src])@W^T + (sum_e attn)*b, so the
// E-scale GEMM collapses to one N-scale GEMM after aggregation.
// ---------------------------------------------------------------------------
extern "C" void kernel_launch(void* const* d_in, const int* in_sizes, int n_in,
                              void* d_out, int out_size) {
    const float* x   = (const float*)d_in[0];
    const void*  ei  = d_in[1];
    const float* sem = (const float*)d_in[2];
    const float* W   = (const float*)d_in[3];
    const float* b   = (const float*)d_in[4];
    float*       out = (float*)d_out;

    int n = in_sizes[0] / D;   // 50000
    int e = in_sizes[1] / 2;   // 800000

    detect_kernel<<<1, 128>>>((const int*)ei, e);
    {
        int tot = (n > D * D) ? n : D * D;
        prep_kernel<<<(tot + 255) / 256, 256>>>(W, n);
    }
    norm_kernel<<<(n + 7) / 8, 256>>>(sem, n);
    hist_kernel<<<(e + 255) / 256, 256>>>(ei, e, n);
    scan_kernel<<<1, 1024>>>(n);
    scatter_kernel<<<(e + 255) / 256, 256>>>(ei, e, n);
    agg_kernel<<<(n + 7) / 8, 256>>>(x, n);
    gemm_kernel<<<(n + GR - 1) / GR, 256>>>(b, out, n);
}

// round 9
// speedup vs baseline: 1.1659x; 1.1659x over previous
#include <cuda_runtime.h>
#include <cuda_fp16.h>
#include <math.h>

// Problem constants (from reference): N=50000, E=800000, dims all 128.
#define MAXN 50000
#define MAXE 800000
#define D 128

// Scratch (no allocations allowed -> __device__ globals).
__device__ __align__(16) uint2  g_semn2[MAXN * 32];  // normalized semantic vecs, fp16 (4/lane)
__device__ __align__(16) float  g_agg[MAXN * D];     // softmax-weighted aggregate per dst
__device__ __align__(16) float  g_Wt[D * D];         // W_src^T: Wt[k*128+j] = W[j*128+k]
__device__ float g_bcoef[MAXN];                      // sum(attn) per dst (~1 or 0)
__device__ int   g_deg[MAXN];
__device__ int   g_offs[MAXN + 1];
__device__ int   g_cursor[MAXN];
__device__ int   g_srcs[MAXE];                       // src ids grouped by dst
__device__ int   g_is64;                             // edge_index dtype flag

// ---- f32x2 packed-math helpers (SASS: FFMA2; only reachable via PTX) ------
__device__ __forceinline__ unsigned long long pk2(float a, float b) {
    unsigned long long r;
    asm("mov.b64 %0, {%1, %2};" : "=l"(r) : "f"(a), "f"(b));
    return r;
}
__device__ __forceinline__ float2 unpk2(unsigned long long v) {
    float2 r;
    asm("mov.b64 {%0, %1}, %2;" : "=f"(r.x), "=f"(r.y) : "l"(v));
    return r;
}
__device__ __forceinline__ void fma2(unsigned long long& d,
                                     unsigned long long a, unsigned long long b) {
    asm("fma.rn.f32x2 %0, %1, %2, %0;" : "+l"(d) : "l"(a), "l"(b));
}

// ---------------------------------------------------------------------------
// K0: zero histogram + transpose W + (block 0) detect edge_index dtype.
// int64 ids < 50000 => every odd 32-bit word is 0; int32 => essentially never.
// ---------------------------------------------------------------------------
__global__ void prep_kernel(const float* __restrict__ W, const int* __restrict__ p32,
                            int n, int e) {
    int i = blockIdx.x * blockDim.x + threadIdx.x;
    if (i < n) g_deg[i] = 0;
    if (i < D * D) {
        int j = i >> 7;      // row of W
        int k = i & 127;     // col of W
        g_Wt[k * D + j] = W[i];
    }
    if (blockIdx.x == 0) {
        __shared__ int nz;
        if (threadIdx.x == 0) nz = 0;
        __syncthreads();
        int idx = 2 * (int)threadIdx.x + 1;          // sample odd words
        if (threadIdx.x < 128 && idx < 2 * e && p32[idx] != 0) atomicAdd(&nz, 1);
        __syncthreads();
        if (threadIdx.x == 0) g_is64 = (nz == 0) ? 1 : 0;
    }
}

// ---------------------------------------------------------------------------
// K1: normalized semantic vectors -> fp16 (warp per node, 4 floats/lane)
// ---------------------------------------------------------------------------
__global__ __launch_bounds__(256) void norm_kernel(const float* __restrict__ sem, int n) {
    int warp = (blockIdx.x * blockDim.x + threadIdx.x) >> 5;
    int lane = threadIdx.x & 31;
    if (warp >= n) return;
    float4 v = ((const float4*)sem)[(size_t)warp * 32 + lane];
    float ss = v.x * v.x + v.y * v.y + v.z * v.z + v.w * v.w;
    #pragma unroll
    for (int o = 16; o; o >>= 1) ss += __shfl_xor_sync(0xffffffffu, ss, o);
    float inv = 1.0f / fmaxf(sqrtf(ss), 1e-8f);
    __half2 h0 = __floats2half2_rn(v.x * inv, v.y * inv);
    __half2 h1 = __floats2half2_rn(v.z * inv, v.w * inv);
    uint2 u;
    u.x = *(const unsigned int*)&h0;
    u.y = *(const unsigned int*)&h1;
    g_semn2[(size_t)warp * 32 + lane] = u;
}

// ---------------------------------------------------------------------------
// K2: degree histogram over dst, 2 edges/thread (range-guarded)
// ---------------------------------------------------------------------------
__global__ void hist_kernel(const void* __restrict__ ei, int e, int n) {
    int i = (blockIdx.x * blockDim.x + threadIdx.x) * 2;
    if (i >= e) return;
    int d0, d1 = -1;
    if (g_is64) {
        const longlong2* p = (const longlong2*)((const long long*)ei + e);
        longlong2 v = p[i >> 1];
        d0 = (int)v.x;
        if (i + 1 < e) d1 = (int)v.y;
    } else {
        const int2* p = (const int2*)((const int*)ei + e);
        int2 v = p[i >> 1];
        d0 = v.x;
        if (i + 1 < e) d1 = v.y;
    }
    if ((unsigned)d0 < (unsigned)n) atomicAdd(&g_deg[d0], 1);
    if ((unsigned)d1 < (unsigned)n) atomicAdd(&g_deg[d1], 1);
}

// ---------------------------------------------------------------------------
// K3: exclusive scan, single pass. 1024 threads; each owns a contiguous chunk,
// serial local sum, two-level shfl scan of the 1024 thread totals, then serial
// prefix writeback. One barrier pair instead of ~1000.
// ---------------------------------------------------------------------------
__global__ __launch_bounds__(1024) void scan_kernel(int n) {
    __shared__ int warp_sums[32];
    int tid = threadIdx.x;
    int C = (n + 1023) / 1024;
    int b0 = tid * C;
    int b1 = min(b0 + C, n);
    int local = 0;
    for (int i = b0; i < b1; ++i) local += g_deg[i];

    int lane = tid & 31, wid = tid >> 5;
    int v = local;
    #pragma unroll
    for (int o = 1; o < 32; o <<= 1) {
        int t = __shfl_up_sync(0xffffffffu, v, o);
        if (lane >= o) v += t;
    }
    if (lane == 31) warp_sums[wid] = v;
    __syncthreads();
    if (wid == 0) {
        int s = warp_sums[lane];
        #pragma unroll
        for (int o = 1; o < 32; o <<= 1) {
            int t = __shfl_up_sync(0xffffffffu, s, o);
            if (lane >= o) s += t;
        }
        warp_sums[lane] = s;
    }
    __syncthreads();
    int excl = (v - local) + (wid ? warp_sums[wid - 1] : 0);
    for (int i = b0; i < b1; ++i) {
        int d = g_deg[i];
        g_offs[i] = excl;
        g_cursor[i] = excl;
        excl += d;
    }
    if (tid == 1023) g_offs[n] = excl;   // thread 1023's chunk is empty -> excl == total
}

// ---------------------------------------------------------------------------
// K4: counting-sort scatter of src ids grouped by dst, 2 edges/thread
// ---------------------------------------------------------------------------
__global__ void scatter_kernel(const void* __restrict__ ei, int e, int n) {
    int i = (blockIdx.x * blockDim.x + threadIdx.x) * 2;
    if (i >= e) return;
    int s0, s1 = -1, d0, d1 = -1;
    if (g_is64) {
        const longlong2* ps = (const longlong2*)ei;
        const longlong2* pd = (const longlong2*)((const long long*)ei + e);
        longlong2 vs = ps[i >> 1], vd = pd[i >> 1];
        s0 = (int)vs.x; d0 = (int)vd.x;
        if (i + 1 < e) { s1 = (int)vs.y; d1 = (int)vd.y; }
    } else {
        const int2* ps = (const int2*)ei;
        const int2* pd = (const int2*)((const int*)ei + e);
        int2 vs = ps[i >> 1], vd = pd[i >> 1];
        s0 = vs.x; d0 = vd.x;
        if (i + 1 < e) { s1 = vs.y; d1 = vd.y; }
    }
    if ((unsigned)s0 < (unsigned)n && (unsigned)d0 < (unsigned)n)
        g_srcs[atomicAdd(&g_cursor[d0], 1)] = s0;
    if ((unsigned)s1 < (unsigned)n && (unsigned)d1 < (unsigned)n)
        g_srcs[atomicAdd(&g_cursor[d1], 1)] = s1;
}

// ---------------------------------------------------------------------------
// K5: per-dst softmax aggregation (warp per dst). Cosine sim is in [-1,1], so
// exp(sim) is unconditionally safe -> no online max, no branches.
// 2-edge manual pipelining: two independent load+shfl chains interleave.
//     agg = (sum_e exp(sim)*x[src]) / (sum_e exp(sim) + 1e-16)
//     bcoef = s / (s + 1e-16)
// ---------------------------------------------------------------------------
__global__ __launch_bounds__(256) void agg_kernel(const float* __restrict__ x, int n) {
    int warp = (blockIdx.x * blockDim.x + threadIdx.x) >> 5;
    int lane = threadIdx.x & 31;
    if (warp >= n) return;
    int beg = g_offs[warp];
    int end = g_offs[warp + 1];

    const float4* x4 = (const float4*)x;

    uint2 du = g_semn2[(size_t)warp * 32 + lane];
    float2 sd0 = __half22float2(*(const __half2*)&du.x);
    float2 sd1 = __half22float2(*(const __half2*)&du.y);

    float s = 0.0f;
    float4 acc = make_float4(0.f, 0.f, 0.f, 0.f);

    int i = beg;
    for (; i + 2 <= end; i += 2) {
        int sA = g_srcs[i], sB = g_srcs[i + 1];
        uint2 uA = g_semn2[(size_t)sA * 32 + lane];
        uint2 uB = g_semn2[(size_t)sB * 32 + lane];
        float4 xA = x4[(size_t)sA * 32 + lane];
        float4 xB = x4[(size_t)sB * 32 + lane];

        float2 a0 = __half22float2(*(const __half2*)&uA.x);
        float2 a1 = __half22float2(*(const __half2*)&uA.y);
        float2 b0 = __half22float2(*(const __half2*)&uB.x);
        float2 b1 = __half22float2(*(const __half2*)&uB.y);

        float pA = sd0.x * a0.x + sd0.y * a0.y + sd1.x * a1.x + sd1.y * a1.y;
        float pB = sd0.x * b0.x + sd0.y * b0.y + sd1.x * b1.x + sd1.y * b1.y;
        #pragma unroll
        for (int o = 16; o; o >>= 1) {
            pA += __shfl_xor_sync(0xffffffffu, pA, o);
            pB += __shfl_xor_sync(0xffffffffu, pB, o);
        }
        float wA = __expf(pA), wB = __expf(pB);
        s += wA + wB;
        acc.x += wA * xA.x + wB * xB.x;
        acc.y += wA * xA.y + wB * xB.y;
        acc.z += wA * xA.z + wB * xB.z;
        acc.w += wA * xA.w + wB * xB.w;
    }
    if (i < end) {
        int sA = g_srcs[i];
        uint2 uA = g_semn2[(size_t)sA * 32 + lane];
        float4 xA = x4[(size_t)sA * 32 + lane];
        float2 a0 = __half22float2(*(const __half2*)&uA.x);
        float2 a1 = __half22float2(*(const __half2*)&uA.y);
        float p = sd0.x * a0.x + sd0.y * a0.y + sd1.x * a1.x + sd1.y * a1.y;
        #pragma unroll
        for (int o = 16; o; o >>= 1) p += __shfl_xor_sync(0xffffffffu, p, o);
        float w = __expf(p);
        s += w;
        acc.x += w * xA.x; acc.y += w * xA.y;
        acc.z += w * xA.z; acc.w += w * xA.w;
    }

    float inv = 1.0f / (s + 1e-16f);
    ((float4*)g_agg)[(size_t)warp * 32 + lane] =
        make_float4(acc.x * inv, acc.y * inv, acc.z * inv, acc.w * inv);
    if (lane == 0) g_bcoef[warp] = s * inv;
}

// ---------------------------------------------------------------------------
// K6: out[r] = agg[r] @ W^T + bcoef[r] * b  using packed f32x2 FMA.
// A staged DUPLICATED in shared as (a,a) float2 pairs -> LDS.64 broadcast
// feeds the fma2 multiplicand with zero packing movs. W pairs packed once/k.
// 32 rows/block, 8 warps x 4 rows; lane owns cols lane*4..lane*4+3.
// fma-pipe issues: 8 fma2 per k per thread vs 16 FFMA before (2x).
// ---------------------------------------------------------------------------
#define GR 32
__global__ __launch_bounds__(256) void gemm_kernel(const float* __restrict__ bias,
                                                   float* __restrict__ out, int n) {
    __shared__ float2 shA2[GR * D];   // 32 KB, duplicated pairs
    __shared__ float  shB[D];

    int tid = threadIdx.x;
    int rbase = blockIdx.x * GR;

    if (tid < D) shB[tid] = bias[tid];
    for (int i = tid; i < GR * 32; i += 256) {        // i indexes float4s of A
        int r = rbase + (i >> 5);
        float4 a = (r < n) ? ((const float4*)g_agg)[(size_t)rbase * 32 + i]
                           : make_float4(0.f, 0.f, 0.f, 0.f);
        ((float4*)shA2)[i * 2 + 0] = make_float4(a.x, a.x, a.y, a.y);
        ((float4*)shA2)[i * 2 + 1] = make_float4(a.z, a.z, a.w, a.w);
    }
    __syncthreads();

    int warp = tid >> 5, lane = tid & 31;
    const float4* Wt4 = (const float4*)g_Wt;
    int r0 = warp * 4;

    unsigned long long acc01[4], acc23[4];
    #pragma unroll
    for (int r = 0; r < 4; r++) { acc01[r] = pk2(0.f, 0.f); acc23[r] = pk2(0.f, 0.f); }

    #pragma unroll 8
    for (int k = 0; k < D; ++k) {
        float4 w = __ldg(&Wt4[k * 32 + lane]);
        unsigned long long w01 = pk2(w.x, w.y);
        unsigned long long w23 = pk2(w.z, w.w);
        #pragma unroll
        for (int r = 0; r < 4; r++) {
            unsigned long long a =
                *(const unsigned long long*)&shA2[(r0 + r) * D + k];  // broadcast
            fma2(acc01[r], a, w01);
            fma2(acc23[r], a, w23);
        }
    }

    #pragma unroll
    for (int r = 0; r < 4; r++) {
        int row = rbase + r0 + r;
        if (row >= n) break;
        float bc = g_bcoef[row];
        float2 e01 = unpk2(acc01[r]);
        float2 e23 = unpk2(acc23[r]);
        float4 o;
        o.x = e01.x + bc * shB[lane * 4 + 0];
        o.y = e01.y + bc * shB[lane * 4 + 1];
        o.z = e23.x + bc * shB[lane * 4 + 2];
        o.w = e23.y + bc * shB[lane * 4 + 3];
        ((float4*)out)[(size_t)row * 32 + lane] = o;
    }
}

// ---------------------------------------------------------------------------
// Launch.
// Inputs (metadata order): x[N,128] f32, edge_index[2,E] (int32 or int64),
//   semantic_vec[N,128] f32, W_src[128,128] f32, b_src[128] f32,
//   W_dst (unused), b_dst (unused).
// Output: out[N,128] f32.
// Algebra: out = (sum_e attn*x[src])@W^T + (sum_e attn)*b  -> the E-scale GEMM
// collapses to one N-scale GEMM after aggregation (16x FLOP reduction).
// ---------------------------------------------------------------------------
extern "C" void kernel_launch(void* const* d_in, const int* in_sizes, int n_in,
                              void* d_out, int out_size) {
    const float* x   = (const float*)d_in[0];
    const void*  ei  = d_in[1];
    const float* sem = (const float*)d_in[2];
    const float* W   = (const float*)d_in[3];
    const float* b   = (const float*)d_in[4];
    float*       out = (float*)d_out;

    int n = in_sizes[0] / D;   // 50000
    int e = in_sizes[1] / 2;   // 800000

    {
        int tot = (n > D * D) ? n : D * D;
        prep_kernel<<<(tot + 255) / 256, 256>>>(W, (const int*)ei, n, e);
    }
    norm_kernel<<<(n + 7) / 8, 256>>>(sem, n);
    hist_kernel<<<(e / 2 + 255) / 256, 256>>>(ei, e, n);
    scan_kernel<<<1, 1024>>>(n);
    scatter_kernel<<<(e / 2 + 255) / 256, 256>>>(ei, e, n);
    agg_kernel<<<(n + 7) / 8, 256>>>(x, n);
    gemm_kernel<<<(n + GR - 1) / GR, 256>>>(b, out, n);
}

// round 12
// speedup vs baseline: 1.6848x; 1.4450x over previous
#include <cuda_runtime.h>
#include <cuda_fp16.h>
#include <math.h>

// Problem constants (from reference): N=50000, E=800000, dims all 128.
#define MAXN 50000
#define MAXE 800000
#define D 128
#define SCAN_BLK 1024
#define MAX_SCAN_BLOCKS 64

// Scratch (no allocations allowed -> __device__ globals).
__device__ __align__(16) uint2  g_semn2[MAXN * 32];  // normalized semantic vecs, fp16 (4/lane)
__device__ __align__(16) float  g_agg[MAXN * D];     // softmax-weighted aggregate per dst
__device__ __align__(16) float  g_Wt[D * D];         // W_src^T: Wt[k*128+j] = W[j*128+k]
__device__ float g_bcoef[MAXN];                      // sum(attn) per dst (~1 or 0)
__device__ int   g_deg[MAXN];
__device__ int   g_offs[MAXN + 1];
__device__ int   g_cursor[MAXN];
__device__ int   g_srcs[MAXE];                       // src ids grouped by dst
__device__ int   g_is64;                             // edge_index dtype flag
__device__ int   g_bsums[MAX_SCAN_BLOCKS];           // per-block sums for 3-phase scan

// ---- f32x2 packed-math helpers (SASS: FFMA2; only reachable via PTX) ------
__device__ __forceinline__ unsigned long long pk2(float a, float b) {
    unsigned long long r;
    asm("mov.b64 %0, {%1, %2};" : "=l"(r) : "f"(a), "f"(b));
    return r;
}
__device__ __forceinline__ float2 unpk2(unsigned long long v) {
    float2 r;
    asm("mov.b64 {%0, %1}, %2;" : "=f"(r.x), "=f"(r.y) : "l"(v));
    return r;
}
__device__ __forceinline__ void fma2(unsigned long long& d,
                                     unsigned long long a, unsigned long long b) {
    asm("fma.rn.f32x2 %0, %1, %2, %0;" : "+l"(d) : "l"(a), "l"(b));
}

// ---------------------------------------------------------------------------
// K0: zero histogram + transpose W + (block 0) detect edge_index dtype.
// int64 ids < 50000 => every odd 32-bit word is 0; int32 => essentially never.
// ---------------------------------------------------------------------------
__global__ void prep_kernel(const float* __restrict__ W, const int* __restrict__ p32,
                            int n, int e) {
    int i = blockIdx.x * blockDim.x + threadIdx.x;
    if (i < n) g_deg[i] = 0;
    if (i < D * D) {
        int j = i >> 7;      // row of W
        int k = i & 127;     // col of W
        g_Wt[k * D + j] = W[i];
    }
    if (blockIdx.x == 0) {
        __shared__ int nz;
        if (threadIdx.x == 0) nz = 0;
        __syncthreads();
        int idx = 2 * (int)threadIdx.x + 1;          // sample odd words
        if (threadIdx.x < 128 && idx < 2 * e && p32[idx] != 0) atomicAdd(&nz, 1);
        __syncthreads();
        if (threadIdx.x == 0) g_is64 = (nz == 0) ? 1 : 0;
    }
}

// ---------------------------------------------------------------------------
// K1: normalized semantic vectors -> fp16 (warp per node, 4 floats/lane)
// ---------------------------------------------------------------------------
__global__ __launch_bounds__(256) void norm_kernel(const float* __restrict__ sem, int n) {
    int warp = (blockIdx.x * blockDim.x + threadIdx.x) >> 5;
    int lane = threadIdx.x & 31;
    if (warp >= n) return;
    float4 v = ((const float4*)sem)[(size_t)warp * 32 + lane];
    float ss = v.x * v.x + v.y * v.y + v.z * v.z + v.w * v.w;
    #pragma unroll
    for (int o = 16; o; o >>= 1) ss += __shfl_xor_sync(0xffffffffu, ss, o);
    float inv = 1.0f / fmaxf(sqrtf(ss), 1e-8f);
    __half2 h0 = __floats2half2_rn(v.x * inv, v.y * inv);
    __half2 h1 = __floats2half2_rn(v.z * inv, v.w * inv);
    uint2 u;
    u.x = *(const unsigned int*)&h0;
    u.y = *(const unsigned int*)&h1;
    g_semn2[(size_t)warp * 32 + lane] = u;
}

// ---------------------------------------------------------------------------
// K2: degree histogram over dst, 2 edges/thread (range-guarded)
// ---------------------------------------------------------------------------
__global__ void hist_kernel(const void* __restrict__ ei, int e, int n) {
    int i = (blockIdx.x * blockDim.x + threadIdx.x) * 2;
    if (i >= e) return;
    int d0, d1 = -1;
    if (g_is64) {
        const longlong2* p = (const longlong2*)((const long long*)ei + e);
        longlong2 v = p[i >> 1];
        d0 = (int)v.x;
        if (i + 1 < e) d1 = (int)v.y;
    } else {
        const int2* p = (const int2*)((const int*)ei + e);
        int2 v = p[i >> 1];
        d0 = v.x;
        if (i + 1 < e) d1 = v.y;
    }
    if ((unsigned)d0 < (unsigned)n) atomicAdd(&g_deg[d0], 1);
    if ((unsigned)d1 < (unsigned)n) atomicAdd(&g_deg[d1], 1);
}

// ---------------------------------------------------------------------------
// K3: grid-wide 3-phase exclusive scan (one element per thread, coalesced).
// a) per-block reduce -> g_bsums;  b) 1 warp scans block sums;  c) per-block
// shfl scan + block offset -> g_offs / g_cursor.
// ---------------------------------------------------------------------------
__global__ __launch_bounds__(SCAN_BLK) void scan_sum_kernel(int n) {
    __shared__ int wsum[32];
    int i = blockIdx.x * SCAN_BLK + threadIdx.x;
    int v = (i < n) ? g_deg[i] : 0;
    int lane = threadIdx.x & 31, wid = threadIdx.x >> 5;
    int s = v;
    #pragma unroll
    for (int o = 16; o; o >>= 1) s += __shfl_xor_sync(0xffffffffu, s, o);
    if (lane == 0) wsum[wid] = s;
    __syncthreads();
    if (wid == 0) {
        int t = wsum[lane];
        #pragma unroll
        for (int o = 16; o; o >>= 1) t += __shfl_xor_sync(0xffffffffu, t, o);
        if (lane == 0) g_bsums[blockIdx.x] = t;
    }
}

__global__ void scan_bsums_kernel(int nblk, int n) {
    // single warp: exclusive scan of up to 32... use 64 lanes? nblk <= 64.
    // Use 2-level within 64 threads (2 warps) via shared.
    __shared__ int sh[MAX_SCAN_BLOCKS];
    int tid = threadIdx.x;
    int v = (tid < nblk) ? g_bsums[tid] : 0;
    sh[tid] = v;
    __syncthreads();
    // simple Hillis-Steele over 64 elements (6 steps)
    #pragma unroll
    for (int o = 1; o < MAX_SCAN_BLOCKS; o <<= 1) {
        int t = (tid >= o) ? sh[tid - o] : 0;
        __syncthreads();
        sh[tid] += t;
        __syncthreads();
    }
    if (tid < nblk) g_bsums[tid] = sh[tid] - v;   // exclusive
    if (tid == MAX_SCAN_BLOCKS - 1) g_offs[n] = sh[tid];  // total
}

__global__ __launch_bounds__(SCAN_BLK) void scan_write_kernel(int n) {
    __shared__ int wsum[32];
    int i = blockIdx.x * SCAN_BLK + threadIdx.x;
    int v = (i < n) ? g_deg[i] : 0;
    int lane = threadIdx.x & 31, wid = threadIdx.x >> 5;
    int incl = v;
    #pragma unroll
    for (int o = 1; o < 32; o <<= 1) {
        int t = __shfl_up_sync(0xffffffffu, incl, o);
        if (lane >= o) incl += t;
    }
    if (lane == 31) wsum[wid] = incl;
    __syncthreads();
    if (wid == 0) {
        int s = wsum[lane];
        #pragma unroll
        for (int o = 1; o < 32; o <<= 1) {
            int t = __shfl_up_sync(0xffffffffu, s, o);
            if (lane >= o) s += t;
        }
        wsum[lane] = s;
    }
    __syncthreads();
    if (i < n) {
        int excl = (incl - v) + (wid ? wsum[wid - 1] : 0) + g_bsums[blockIdx.x];
        g_offs[i] = excl;
        g_cursor[i] = excl;
    }
}

// ---------------------------------------------------------------------------
// K4: counting-sort scatter of src ids grouped by dst, 2 edges/thread
// ---------------------------------------------------------------------------
__global__ void scatter_kernel(const void* __restrict__ ei, int e, int n) {
    int i = (blockIdx.x * blockDim.x + threadIdx.x) * 2;
    if (i >= e) return;
    int s0, s1 = -1, d0, d1 = -1;
    if (g_is64) {
        const longlong2* ps = (const longlong2*)ei;
        const longlong2* pd = (const longlong2*)((const long long*)ei + e);
        longlong2 vs = ps[i >> 1], vd = pd[i >> 1];
        s0 = (int)vs.x; d0 = (int)vd.x;
        if (i + 1 < e) { s1 = (int)vs.y; d1 = (int)vd.y; }
    } else {
        const int2* ps = (const int2*)ei;
        const int2* pd = (const int2*)((const int*)ei + e);
        int2 vs = ps[i >> 1], vd = pd[i >> 1];
        s0 = vs.x; d0 = vd.x;
        if (i + 1 < e) { s1 = vs.y; d1 = vd.y; }
    }
    if ((unsigned)s0 < (unsigned)n && (unsigned)d0 < (unsigned)n)
        g_srcs[atomicAdd(&g_cursor[d0], 1)] = s0;
    if ((unsigned)s1 < (unsigned)n && (unsigned)d1 < (unsigned)n)
        g_srcs[atomicAdd(&g_cursor[d1], 1)] = s1;
}

// ---------------------------------------------------------------------------
// K5: per-dst softmax aggregation (warp per dst). Cosine sim is in [-1,1], so
// exp(sim) is unconditionally safe -> no online max, no branches.
// 2-edge manual pipelining: two independent load+shfl chains interleave.
//     agg = (sum_e exp(sim)*x[src]) / (sum_e exp(sim) + 1e-16)
//     bcoef = s / (s + 1e-16)
// ---------------------------------------------------------------------------
__global__ __launch_bounds__(256) void agg_kernel(const float* __restrict__ x, int n) {
    int warp = (blockIdx.x * blockDim.x + threadIdx.x) >> 5;
    int lane = threadIdx.x & 31;
    if (warp >= n) return;
    int beg = g_offs[warp];
    int end = g_offs[warp + 1];

    const float4* x4 = (const float4*)x;

    uint2 du = g_semn2[(size_t)warp * 32 + lane];
    float2 sd0 = __half22float2(*(const __half2*)&du.x);
    float2 sd1 = __half22float2(*(const __half2*)&du.y);

    float s = 0.0f;
    float4 acc = make_float4(0.f, 0.f, 0.f, 0.f);

    int i = beg;
    for (; i + 2 <= end; i += 2) {
        int sA = g_srcs[i], sB = g_srcs[i + 1];
        uint2 uA = g_semn2[(size_t)sA * 32 + lane];
        uint2 uB = g_semn2[(size_t)sB * 32 + lane];
        float4 xA = x4[(size_t)sA * 32 + lane];
        float4 xB = x4[(size_t)sB * 32 + lane];

        float2 a0 = __half22float2(*(const __half2*)&uA.x);
        float2 a1 = __half22float2(*(const __half2*)&uA.y);
        float2 b0 = __half22float2(*(const __half2*)&uB.x);
        float2 b1 = __half22float2(*(const __half2*)&uB.y);

        float pA = sd0.x * a0.x + sd0.y * a0.y + sd1.x * a1.x + sd1.y * a1.y;
        float pB = sd0.x * b0.x + sd0.y * b0.y + sd1.x * b1.x + sd1.y * b1.y;
        #pragma unroll
        for (int o = 16; o; o >>= 1) {
            pA += __shfl_xor_sync(0xffffffffu, pA, o);
            pB += __shfl_xor_sync(0xffffffffu, pB, o);
        }
        float wA = __expf(pA), wB = __expf(pB);
        s += wA + wB;
        acc.x += wA * xA.x + wB * xB.x;
        acc.y += wA * xA.y + wB * xB.y;
        acc.z += wA * xA.z + wB * xB.z;
        acc.w += wA * xA.w + wB * xB.w;
    }
    if (i < end) {
        int sA = g_srcs[i];
        uint2 uA = g_semn2[(size_t)sA * 32 + lane];
        float4 xA = x4[(size_t)sA * 32 + lane];
        float2 a0 = __half22float2(*(const __half2*)&uA.x);
        float2 a1 = __half22float2(*(const __half2*)&uA.y);
        float p = sd0.x * a0.x + sd0.y * a0.y + sd1.x * a1.x + sd1.y * a1.y;
        #pragma unroll
        for (int o = 16; o; o >>= 1) p += __shfl_xor_sync(0xffffffffu, p, o);
        float w = __expf(p);
        s += w;
        acc.x += w * xA.x; acc.y += w * xA.y;
        acc.z += w * xA.z; acc.w += w * xA.w;
    }

    float inv = 1.0f / (s + 1e-16f);
    ((float4*)g_agg)[(size_t)warp * 32 + lane] =
        make_float4(acc.x * inv, acc.y * inv, acc.z * inv, acc.w * inv);
    if (lane == 0) g_bcoef[warp] = s * inv;
}

// ---------------------------------------------------------------------------
// K6: out[r] = agg[r] @ W^T + bcoef[r] * b  using packed f32x2 FMA.
// A staged DUPLICATED in shared as (a,a) float2 pairs -> LDS.64 broadcast
// feeds the fma2 multiplicand with zero packing movs. W pairs packed once/k.
// 32 rows/block, 8 warps x 4 rows; lane owns cols lane*4..lane*4+3.
// ---------------------------------------------------------------------------
#define GR 32
__global__ __launch_bounds__(256) void gemm_kernel(const float* __restrict__ bias,
                                                   float* __restrict__ out, int n) {
    __shared__ float2 shA2[GR * D];   // 32 KB, duplicated pairs
    __shared__ float  shB[D];

    int tid = threadIdx.x;
    int rbase = blockIdx.x * GR;

    if (tid < D) shB[tid] = bias[tid];
    for (int i = tid; i < GR * 32; i += 256) {        // i indexes float4s of A
        int r = rbase + (i >> 5);
        float4 a = (r < n) ? ((const float4*)g_agg)[(size_t)rbase * 32 + i]
                           : make_float4(0.f, 0.f, 0.f, 0.f);
        ((float4*)shA2)[i * 2 + 0] = make_float4(a.x, a.x, a.y, a.y);
        ((float4*)shA2)[i * 2 + 1] = make_float4(a.z, a.z, a.w, a.w);
    }
    __syncthreads();

    int warp = tid >> 5, lane = tid & 31;
    const float4* Wt4 = (const float4*)g_Wt;
    int r0 = warp * 4;

    unsigned long long acc01[4], acc23[4];
    #pragma unroll
    for (int r = 0; r < 4; r++) { acc01[r] = pk2(0.f, 0.f); acc23[r] = pk2(0.f, 0.f); }

    #pragma unroll 8
    for (int k = 0; k < D; ++k) {
        float4 w = __ldg(&Wt4[k * 32 + lane]);
        unsigned long long w01 = pk2(w.x, w.y);
        unsigned long long w23 = pk2(w.z, w.w);
        #pragma unroll
        for (int r = 0; r < 4; r++) {
            unsigned long long a =
                *(const unsigned long long*)&shA2[(r0 + r) * D + k];  // broadcast
            fma2(acc01[r], a, w01);
            fma2(acc23[r], a, w23);
        }
    }

    #pragma unroll
    for (int r = 0; r < 4; r++) {
        int row = rbase + r0 + r;
        if (row >= n) break;
        float bc = g_bcoef[row];
        float2 e01 = unpk2(acc01[r]);
        float2 e23 = unpk2(acc23[r]);
        float4 o;
        o.x = e01.x + bc * shB[lane * 4 + 0];
        o.y = e01.y + bc * shB[lane * 4 + 1];
        o.z = e23.x + bc * shB[lane * 4 + 2];
        o.w = e23.y + bc * shB[lane * 4 + 3];
        ((float4*)out)[(size_t)row * 32 + lane] = o;
    }
}

// ---------------------------------------------------------------------------
// Launch.
// Inputs (metadata order): x[N,128] f32, edge_index[2,E] (int32 or int64),
//   semantic_vec[N,128] f32, W_src[128,128] f32, b_src[128] f32,
//   W_dst (unused), b_dst (unused).
// Output: out[N,128] f32.
// Algebra: out = (sum_e attn*x[src])@W^T + (sum_e attn)*b  -> the E-scale GEMM
// collapses to one N-scale GEMM after aggregation (16x FLOP reduction).
// ---------------------------------------------------------------------------
extern "C" void kernel_launch(void* const* d_in, const int* in_sizes, int n_in,
                              void* d_out, int out_size) {
    const float* x   = (const float*)d_in[0];
    const void*  ei  = d_in[1];
    const float* sem = (const float*)d_in[2];
    const float* W   = (const float*)d_in[3];
    const float* b   = (const float*)d_in[4];
    float*       out = (float*)d_out;

    int n = in_sizes[0] / D;   // 50000
    int e = in_sizes[1] / 2;   // 800000

    int nblk = (n + SCAN_BLK - 1) / SCAN_BLK;   // 49 <= 64

    {
        int tot = (n > D * D) ? n : D * D;
        prep_kernel<<<(tot + 255) / 256, 256>>>(W, (const int*)ei, n, e);
    }
    norm_kernel<<<(n + 7) / 8, 256>>>(sem, n);
    hist_kernel<<<(e / 2 + 255) / 256, 256>>>(ei, e, n);
    scan_sum_kernel<<<nblk, SCAN_BLK>>>(n);
    scan_bsums_kernel<<<1, MAX_SCAN_BLOCKS>>>(nblk, n);
    scan_write_kernel<<<nblk, SCAN_BLK>>>(n);
    scatter_kernel<<<(e / 2 + 255) / 256, 256>>>(ei, e, n);
    agg_kernel<<<(n + 7) / 8, 256>>>(x, n);
    gemm_kernel<<<(n + GR - 1) / GR, 256>>>(b, out, n);
}